// round 7
// baseline (speedup 1.0000x reference)
#include <cuda_runtime.h>
#include <math.h>
#include <stdint.h>

static constexpr int TT  = 512;
static constexpr int NB  = 32;
static constexpr int DIN = 41;
static constexpr int HH  = 800;
static constexpr int HG  = 3200;   // 4H
static constexpr int HC  = 1600;   // 2H
static constexpr int NA  = 20;

// scratch (device globals; allocation is forbidden)
__device__ float g_bufA[(size_t)TT * NB * HG];
__device__ float g_bufB[(size_t)TT * NB * HG];
__device__ float g_h1[(size_t)TT * NB * HC];
__device__ float g_h2[(size_t)TT * NB * HC];
__device__ float g_ang[(size_t)TT * NB * 3];
__device__ unsigned g_ctr[4];

__global__ void init_kernel() {
    if (threadIdx.x < 4) g_ctr[threadIdx.x] = 0u;
}

__device__ __forceinline__ float sigm(float x) { return 1.0f / (1.0f + expf(-x)); }
__device__ __forceinline__ float tanh_acc(float x) {
    float e = expf(-2.0f * fabsf(x));
    return copysignf((1.0f - e) / (1.0f + e), x);
}

// ---------------- SGEMM: C[M,N] = A[M,K] @ W[N,K]^T + bias[N] ---------------
__global__ __launch_bounds__(256) void gemm_bias(
    const float* __restrict__ A, const float* __restrict__ W,
    const float* __restrict__ bias, float* __restrict__ C,
    int M, int N, int K)
{
    __shared__ __align__(16) float As[16][132];
    __shared__ __align__(16) float Ws[16][68];
    const int bm = blockIdx.y * 128, bn = blockIdx.x * 64;
    const int tid = threadIdx.x, tx = tid & 15, ty = tid >> 4;

    float acc[8][4];
#pragma unroll
    for (int i = 0; i < 8; i++)
#pragma unroll
        for (int j = 0; j < 4; j++) acc[i][j] = 0.0f;

    for (int k0 = 0; k0 < K; k0 += 16) {
#pragma unroll
        for (int i = 0; i < 8; i++) {
            int e = i * 256 + tid, m = e >> 4, kk = e & 15;
            int gm = bm + m, gk = k0 + kk;
            As[kk][m] = (gm < M && gk < K) ? A[(size_t)gm * K + gk] : 0.0f;
        }
#pragma unroll
        for (int i = 0; i < 4; i++) {
            int e = i * 256 + tid, n = e >> 4, kk = e & 15;
            int gn = bn + n, gk = k0 + kk;
            Ws[kk][n] = (gn < N && gk < K) ? W[(size_t)gn * K + gk] : 0.0f;
        }
        __syncthreads();
#pragma unroll
        for (int kk = 0; kk < 16; kk++) {
            float4 a0 = *(const float4*)&As[kk][ty * 8];
            float4 a1 = *(const float4*)&As[kk][ty * 8 + 4];
            float4 wv = *(const float4*)&Ws[kk][tx * 4];
            float am[8] = {a0.x,a0.y,a0.z,a0.w,a1.x,a1.y,a1.z,a1.w};
            float wn[4] = {wv.x,wv.y,wv.z,wv.w};
#pragma unroll
            for (int i = 0; i < 8; i++)
#pragma unroll
                for (int j = 0; j < 4; j++) acc[i][j] += am[i] * wn[j];
        }
        __syncthreads();
    }
#pragma unroll
    for (int j = 0; j < 4; j++) {
        int gn = bn + tx * 4 + j;
        if (gn >= N) continue;
        float bb = bias[gn];
#pragma unroll
        for (int i = 0; i < 8; i++) {
            int gm = bm + ty * 8 + i;
            if (gm < M) C[(size_t)gm * N + gn] = acc[i][j] + bb;
        }
    }
}

// ---------------- persistent bi-LSTM layer ----------------------------------
static constexpr int GPD  = 74;
static constexpr int KP   = 804;
static constexpr int RMAX = 48;
static constexpr int LSTM_SMEM = (RMAX * KP + 32 * 33 + RMAX * 33 + 12 * 32) * 4;

__global__ __launch_bounds__(128) void lstm_kernel(
    const float* __restrict__ xs_f, const float* __restrict__ xs_b,
    const float* __restrict__ Whh_f, const float* __restrict__ Whh_b,
    float* __restrict__ hout, unsigned* __restrict__ ctr)
{
    extern __shared__ float smem_[];
    float* Wsm = smem_;
    float* hA  = Wsm + RMAX * KP;
    float* gsm = hA + 32 * 33;
    float* csm = gsm + RMAX * 33;

    const int dir = blockIdx.x / GPD;
    const int g   = blockIdx.x - dir * GPD;
    const float* xs  = dir ? xs_b : xs_f;
    const float* Whh = dir ? Whh_b : Whh_f;
    const int dirOff = dir ? HH : 0;
    unsigned* myc = ctr + dir;

    const int S  = (g < 60) ? 11 : 10;
    const int j0 = (g < 60) ? g * 11 : 660 + (g - 60) * 10;
    const int R  = 4 * S;
    const int tid = threadIdx.x;

    for (int r = 0; r < RMAX; r++) {
        if (r < R) {
            int gi = r / S, jl = r - gi * S;
            const float* src = Whh + (size_t)(gi * HH + j0 + jl) * HH;
            for (int k = tid; k < HH; k += 128) Wsm[r * KP + k] = src[k];
        } else {
            for (int k = tid; k < HH; k += 128) Wsm[r * KP + k] = 0.0f;
        }
    }
    __syncthreads();

    const int rg = tid >> 3;  // 0..15 -> rows rg*3 .. rg*3+2
    const int bg = tid & 7;   // 0..7  -> batches bg*4 .. bg*4+3

    for (int s = 0; s < TT; s++) {
        const int t = dir ? (TT - 1 - s) : s;
        float acc[3][4];
#pragma unroll
        for (int q = 0; q < 3; q++)
#pragma unroll
            for (int j = 0; j < 4; j++) acc[q][j] = 0.0f;

        if (s > 0) {
            const int tp = dir ? (t + 1) : (t - 1);
            const float* hsrc = hout + (size_t)tp * NB * HC + dirOff;
            float pre[8];
#pragma unroll
            for (int i = 0; i < 8; i++) {
                int e = i * 128 + tid, b = e >> 5, kk = e & 31;
                pre[i] = hsrc[(size_t)b * HC + kk];
            }
            for (int kc = 0; kc < 25; kc++) {
#pragma unroll
                for (int i = 0; i < 8; i++) {
                    int e = i * 128 + tid, b = e >> 5, kk = e & 31;
                    hA[b * 33 + kk] = pre[i];
                }
                __syncthreads();
                if (kc < 24) {
                    const float* p = hsrc + (kc + 1) * 32;
#pragma unroll
                    for (int i = 0; i < 8; i++) {
                        int e = i * 128 + tid, b = e >> 5, kk = e & 31;
                        pre[i] = p[(size_t)b * HC + kk];
                    }
                }
                const float* w0 = Wsm + kc * 32 + (rg * 3 + 0) * KP;
                const float* w1 = Wsm + kc * 32 + (rg * 3 + 1) * KP;
                const float* w2 = Wsm + kc * 32 + (rg * 3 + 2) * KP;
                const float* hb = hA + (bg * 4) * 33;
#pragma unroll 8
                for (int kk = 0; kk < 32; kk++) {
                    float wa = w0[kk], wb = w1[kk], wc = w2[kk];
                    float h0 = hb[kk], h1 = hb[33 + kk];
                    float h2 = hb[66 + kk], h3 = hb[99 + kk];
                    acc[0][0] += wa*h0; acc[0][1] += wa*h1; acc[0][2] += wa*h2; acc[0][3] += wa*h3;
                    acc[1][0] += wb*h0; acc[1][1] += wb*h1; acc[1][2] += wb*h2; acc[1][3] += wb*h3;
                    acc[2][0] += wc*h0; acc[2][1] += wc*h1; acc[2][2] += wc*h2; acc[2][3] += wc*h3;
                }
                __syncthreads();
            }
        }

        const float* xrow = xs + (size_t)t * NB * HG;
#pragma unroll
        for (int q = 0; q < 3; q++) {
            int r = rg * 3 + q;
            if (r < R) {
                int gi = r / S, jl = r - gi * S;
                int grow = gi * HH + j0 + jl;
#pragma unroll
                for (int bi = 0; bi < 4; bi++) {
                    int b = bg * 4 + bi;
                    gsm[r * 33 + b] = acc[q][bi] + xrow[(size_t)b * HG + grow];
                }
            }
        }
        __syncthreads();

        for (int it = tid; it < S * 32; it += 128) {
            int jl = it >> 5, b = it & 31;
            float gi = gsm[(0 * S + jl) * 33 + b];
            float gf = gsm[(1 * S + jl) * 33 + b];
            float gg = gsm[(2 * S + jl) * 33 + b];
            float go = gsm[(3 * S + jl) * 33 + b];
            float c  = (s == 0) ? 0.0f : csm[it];
            float cn = sigm(gf) * c + sigm(gi) * tanh_acc(gg);
            float hn = sigm(go) * tanh_acc(cn);
            csm[it] = cn;
            hout[(size_t)t * NB * HC + (size_t)b * HC + dirOff + j0 + jl] = hn;
        }
        __threadfence();
        __syncthreads();
        if (tid == 0) {
            atomicAdd(myc, 1u);
            unsigned tgt = (unsigned)(s + 1) * (unsigned)GPD;
            while (*((volatile unsigned*)myc) < tgt) { }
            __threadfence();
        }
        __syncthreads();
    }
}

// ---------------- logits -> softmax -> dihedral angles ----------------------
__global__ __launch_bounds__(128) void head_kernel(
    const float* __restrict__ h2, const float* __restrict__ Wl,
    const float* __restrict__ bl, const float* __restrict__ alph,
    float* __restrict__ ang)
{
    __shared__ float row[HC];
    __shared__ float lg[24];
    const int m = blockIdx.x;
    const float* src = h2 + (size_t)m * HC;
    for (int k = threadIdx.x; k < HC; k += 128) row[k] = src[k];
    __syncthreads();

    const int w = threadIdx.x >> 5, lane = threadIdx.x & 31;
    for (int a = w; a < NA; a += 4) {
        const float* wr = Wl + (size_t)a * HC;
        float sum = 0.0f;
        for (int k = lane; k < HC; k += 32) sum += row[k] * wr[k];
#pragma unroll
        for (int o = 16; o; o >>= 1) sum += __shfl_xor_sync(0xffffffffu, sum, o);
        if (lane == 0) lg[a] = sum + bl[a];
    }
    __syncthreads();

    if (threadIdx.x < 32) {
        int a = threadIdx.x;
        float l = (a < NA) ? lg[a] : -1e30f;
        float mx = l;
#pragma unroll
        for (int o = 16; o; o >>= 1) mx = fmaxf(mx, __shfl_xor_sync(0xffffffffu, mx, o));
        float e = (a < NA) ? expf(l - mx) : 0.0f;
        float ss = e;
#pragma unroll
        for (int o = 16; o; o >>= 1) ss += __shfl_xor_sync(0xffffffffu, ss, o);
        float p = e / ss;
#pragma unroll
        for (int k = 0; k < 3; k++) {
            float sy = 0.0f, sx = 0.0f;
            if (a < NA) {
                float al = alph[a * 3 + k];
                sy = p * sinf(al);
                sx = p * cosf(al);
            }
#pragma unroll
            for (int o = 16; o; o >>= 1) {
                sy += __shfl_xor_sync(0xffffffffu, sy, o);
                sx += __shfl_xor_sync(0xffffffffu, sx, o);
            }
            if (a == 0) ang[(size_t)m * 3 + k] = atan2f(sy, sx);
        }
    }
}

// ---------------- NeRF coordinate chain (fp64, one thread per batch) --------
__global__ __launch_bounds__(32) void coords_kernel(
    const float* __restrict__ ang, float* __restrict__ out)
{
    const int b = threadIdx.x;
    if (b >= NB) return;
    const double blen[3] = {1.458, 1.525, 1.33};
    const double bangv[3] = {2.124, 1.941, 2.028};
    double ax=0, ay=0, az=0, bx=1.458, by=0, bz=0, cx=2.0, cy=1.0, cz=0;

    for (int t = 0; t < TT; t++) {
#pragma unroll
        for (int k = 0; k < 3; k++) {
            double phi = (double)ang[((size_t)t * NB + b) * 3 + k];
            double rr = blen[k], tt = bangv[k];
            double ux = cx - bx, uy = cy - by, uz = cz - bz;
            double inv = 1.0 / sqrt(ux*ux + uy*uy + uz*uz);
            ux *= inv; uy *= inv; uz *= inv;
            double vx = bx - ax, vy = by - ay, vz = bz - az;
            double nx = vy*uz - vz*uy, ny = vz*ux - vx*uz, nz = vx*uy - vy*ux;
            inv = 1.0 / sqrt(nx*nx + ny*ny + nz*nz);
            nx *= inv; ny *= inv; nz *= inv;
            double mx = ny*uz - nz*uy, my = nz*ux - nx*uz, mz = nx*uy - ny*ux;
            double cp = cos(phi), sp = sin(phi);
            double rct = rr * cos(tt), rst = rr * sin(tt);
            double dx = cx - rct*ux + rst*(cp*mx + sp*nx);
            double dy = cy - rct*uy + rst*(cp*my + sp*ny);
            double dz = cz - rct*uz + rst*(cp*mz + sp*nz);
            size_t i = (size_t)(t * 3 + k);
            out[(i * NB + b) * 3 + 0] = (float)dx;
            out[(i * NB + b) * 3 + 1] = (float)dy;
            out[(i * NB + b) * 3 + 2] = (float)dz;
            ax = bx; ay = by; az = bz;
            bx = cx; by = cy; bz = cz;
            cx = dx; cy = dy; cz = dz;
        }
    }
}

extern "C" void kernel_launch(void* const* d_in, const int* in_sizes, int n_in,
                              void* d_out, int out_size) {
    const float* x       = (const float*)d_in[0];
    const float* Wih_f0  = (const float*)d_in[1];
    const float* Whh_f0  = (const float*)d_in[2];
    const float* b_f0    = (const float*)d_in[3];
    const float* Wih_b0  = (const float*)d_in[4];
    const float* Whh_b0  = (const float*)d_in[5];
    const float* b_b0    = (const float*)d_in[6];
    const float* Wih_f1  = (const float*)d_in[7];
    const float* Whh_f1  = (const float*)d_in[8];
    const float* b_f1    = (const float*)d_in[9];
    const float* Wih_b1  = (const float*)d_in[10];
    const float* Whh_b1  = (const float*)d_in[11];
    const float* b_b1    = (const float*)d_in[12];
    const float* Wl      = (const float*)d_in[13];
    const float* bl      = (const float*)d_in[14];
    const float* alph    = (const float*)d_in[15];
    float* out = (float*)d_out;

    float *bufA, *bufB, *h1, *h2, *ang;
    unsigned* ctr;
    cudaGetSymbolAddress((void**)&bufA, g_bufA);
    cudaGetSymbolAddress((void**)&bufB, g_bufB);
    cudaGetSymbolAddress((void**)&h1,   g_h1);
    cudaGetSymbolAddress((void**)&h2,   g_h2);
    cudaGetSymbolAddress((void**)&ang,  g_ang);
    cudaGetSymbolAddress((void**)&ctr,  g_ctr);

    cudaFuncSetAttribute(lstm_kernel,
                         cudaFuncAttributeMaxDynamicSharedMemorySize, LSTM_SMEM);

    const int M = TT * NB;
    dim3 gdim(HG / 64, M / 128);

    init_kernel<<<1, 32>>>();
    gemm_bias<<<gdim, 256>>>(x, Wih_f0, b_f0, bufA, M, HG, DIN);
    gemm_bias<<<gdim, 256>>>(x, Wih_b0, b_b0, bufB, M, HG, DIN);
    lstm_kernel<<<2 * GPD, 128, LSTM_SMEM>>>(bufA, bufB, Whh_f0, Whh_b0, h1, ctr);
    gemm_bias<<<gdim, 256>>>(h1, Wih_f1, b_f1, bufA, M, HG, HC);
    gemm_bias<<<gdim, 256>>>(h1, Wih_b1, b_b1, bufB, M, HG, HC);
    lstm_kernel<<<2 * GPD, 128, LSTM_SMEM>>>(bufA, bufB, Whh_f1, Whh_b1, h2, ctr + 2);
    head_kernel<<<M, 128>>>(h2, Wl, bl, alph, ang);
    coords_kernel<<<1, 32>>>(ang, out);
}

// round 9
// speedup vs baseline: 1.3174x; 1.3174x over previous
#include <cuda_runtime.h>
#include <math.h>
#include <stdint.h>

typedef unsigned long long u64;
typedef unsigned int u32;

static constexpr int TT  = 512;
static constexpr int NB  = 32;
static constexpr int DIN = 41;
static constexpr int HH  = 800;
static constexpr int HG  = 3200;   // 4H
static constexpr int HC  = 1600;   // 2H
static constexpr int NA  = 20;

// scratch (device globals; allocation is forbidden)
__device__ __align__(16) float g_bufA[(size_t)TT * NB * HG];
__device__ __align__(16) float g_bufB[(size_t)TT * NB * HG];
__device__ __align__(16) float g_h1[(size_t)TT * NB * HC];
__device__ __align__(16) float g_h2[(size_t)TT * NB * HC];
__device__ __align__(16) float g_sc[(size_t)TT * NB * 6];   // (sy,sx) per angle
__device__ unsigned g_ctr[4];

__global__ void init_kernel() {
    if (threadIdx.x < 4) g_ctr[threadIdx.x] = 0u;
}

__device__ __forceinline__ float sigm(float x) { return 1.0f / (1.0f + expf(-x)); }
__device__ __forceinline__ float tanh_acc(float x) {
    float e = expf(-2.0f * fabsf(x));
    return copysignf((1.0f - e) / (1.0f + e), x);
}

// ---- packed f32x2 helpers (Blackwell FFMA2 path) ---------------------------
__device__ __forceinline__ void fma2(u64& acc, u64 a, u64 b) {
    asm("fma.rn.f32x2 %0, %1, %2, %0;" : "+l"(acc) : "l"(a), "l"(b));
}
__device__ __forceinline__ u64 pack2(float x, float y) {
    u64 r; asm("mov.b64 %0, {%1, %2};" : "=l"(r) : "f"(x), "f"(y)); return r;
}
__device__ __forceinline__ float2 unpack2(u64 v) {
    float2 f; asm("mov.b64 {%0, %1}, %2;" : "=f"(f.x), "=f"(f.y) : "l"(v)); return f;
}
__device__ __forceinline__ u64 lds64(u32 a) {
    u64 r; asm volatile("ld.shared.b64 %0, [%1];" : "=l"(r) : "r"(a)); return r;
}
__device__ __forceinline__ void lds128_2(u64& x, u64& y, u32 a) {
    asm volatile("ld.shared.v2.b64 {%0, %1}, [%2];" : "=l"(x), "=l"(y) : "r"(a));
}

// ---------------- SGEMM (f32x2): C[M,N] = A[M,K] @ W[N,K]^T + bias[N] -------
// 256x128 tile, BK=16, 256 threads, 16m x 8n microtile, m-pair packed accs.
__device__ __forceinline__ void fetch_tileA(
    const float* __restrict__ A, int M, int K, int bm, int k0, int tid,
    bool vec, float4 av[4])
{
#pragma unroll
    for (int i = 0; i < 4; i++) {
        int e = i * 256 + tid, m = e >> 2, c4 = e & 3;
        int gm = bm + m, gk = k0 + c4 * 4;
        const float* p = A + (size_t)gm * K + gk;
        if (vec && gk + 4 <= K) av[i] = *(const float4*)p;
        else {
            float r[4];
#pragma unroll
            for (int u = 0; u < 4; u++) r[u] = (gk + u < K) ? p[u] : 0.0f;
            av[i] = make_float4(r[0], r[1], r[2], r[3]);
        }
    }
}
__device__ __forceinline__ void fetch_tileW(
    const float* __restrict__ W, int N, int K, int bn, int k0, int tid,
    bool vec, float4 wv[2])
{
#pragma unroll
    for (int i = 0; i < 2; i++) {
        int e = i * 256 + tid, n = e >> 2, c4 = e & 3;
        int gn = bn + n, gk = k0 + c4 * 4;
        const float* p = W + (size_t)gn * K + gk;
        if (vec && gk + 4 <= K) wv[i] = *(const float4*)p;
        else {
            float r[4];
#pragma unroll
            for (int u = 0; u < 4; u++) r[u] = (gk + u < K) ? p[u] : 0.0f;
            wv[i] = make_float4(r[0], r[1], r[2], r[3]);
        }
    }
}

__global__ __launch_bounds__(256) void gemm_bias(
    const float* __restrict__ A, const float* __restrict__ W,
    const float* __restrict__ bias, float* __restrict__ C,
    int M, int N, int K)
{
    __shared__ __align__(16) float As[16][260];
    __shared__ __align__(16) float Ws[16][132];
    const int bm = blockIdx.y * 256, bn = blockIdx.x * 128;
    const int tid = threadIdx.x, tx = tid & 15, ty = tid >> 4;
    const bool vec = ((K & 3) == 0);

    u64 acc[8][8];
#pragma unroll
    for (int i = 0; i < 8; i++)
#pragma unroll
        for (int j = 0; j < 8; j++) acc[i][j] = 0ull;

    const int nch = (K + 15) / 16;
    float4 av[4], wv[2];
    fetch_tileA(A, M, K, bm, 0, tid, vec, av);
    fetch_tileW(W, N, K, bn, 0, tid, vec, wv);
#pragma unroll
    for (int i = 0; i < 4; i++) {
        int e = i * 256 + tid, m = e >> 2, c4 = e & 3;
        As[c4*4+0][m] = av[i].x; As[c4*4+1][m] = av[i].y;
        As[c4*4+2][m] = av[i].z; As[c4*4+3][m] = av[i].w;
    }
#pragma unroll
    for (int i = 0; i < 2; i++) {
        int e = i * 256 + tid, n = e >> 2, c4 = e & 3;
        Ws[c4*4+0][n] = wv[i].x; Ws[c4*4+1][n] = wv[i].y;
        Ws[c4*4+2][n] = wv[i].z; Ws[c4*4+3][n] = wv[i].w;
    }
    __syncthreads();

    const u32 asA = (u32)__cvta_generic_to_shared(&As[0][0]) + (u32)(ty * 64);

    for (int c = 0; c < nch; c++) {
        float4 av2[4], wv2[2];
        if (c + 1 < nch) {
            fetch_tileA(A, M, K, bm, (c + 1) * 16, tid, vec, av2);
            fetch_tileW(W, N, K, bn, (c + 1) * 16, tid, vec, wv2);
        }
#pragma unroll
        for (int kk = 0; kk < 16; kk++) {
            u64 a[8];
            u32 aa = asA + (u32)(kk * 1040);
            lds128_2(a[0], a[1], aa);
            lds128_2(a[2], a[3], aa + 16);
            lds128_2(a[4], a[5], aa + 32);
            lds128_2(a[6], a[7], aa + 48);
            float4 w0 = *(const float4*)&Ws[kk][tx * 8];
            float4 w1 = *(const float4*)&Ws[kk][tx * 8 + 4];
            u64 wd[8];
            wd[0] = pack2(w0.x, w0.x); wd[1] = pack2(w0.y, w0.y);
            wd[2] = pack2(w0.z, w0.z); wd[3] = pack2(w0.w, w0.w);
            wd[4] = pack2(w1.x, w1.x); wd[5] = pack2(w1.y, w1.y);
            wd[6] = pack2(w1.z, w1.z); wd[7] = pack2(w1.w, w1.w);
#pragma unroll
            for (int mp = 0; mp < 8; mp++)
#pragma unroll
                for (int j = 0; j < 8; j++) fma2(acc[mp][j], a[mp], wd[j]);
        }
        __syncthreads();
        if (c + 1 < nch) {
#pragma unroll
            for (int i = 0; i < 4; i++) {
                int e = i * 256 + tid, m = e >> 2, c4 = e & 3;
                As[c4*4+0][m] = av2[i].x; As[c4*4+1][m] = av2[i].y;
                As[c4*4+2][m] = av2[i].z; As[c4*4+3][m] = av2[i].w;
            }
#pragma unroll
            for (int i = 0; i < 2; i++) {
                int e = i * 256 + tid, n = e >> 2, c4 = e & 3;
                Ws[c4*4+0][n] = wv2[i].x; Ws[c4*4+1][n] = wv2[i].y;
                Ws[c4*4+2][n] = wv2[i].z; Ws[c4*4+3][n] = wv2[i].w;
            }
            __syncthreads();
        }
    }

    const int gn = bn + tx * 8;
    float bb[8];
#pragma unroll
    for (int j = 0; j < 8; j++) bb[j] = bias[gn + j];
#pragma unroll
    for (int mp = 0; mp < 8; mp++) {
        float2 v[8];
#pragma unroll
        for (int j = 0; j < 8; j++) v[j] = unpack2(acc[mp][j]);
        int gm = bm + ty * 16 + mp * 2;
        float* p0 = C + (size_t)gm * N + gn;
        float* p1 = p0 + N;
        float4 l0 = make_float4(v[0].x+bb[0], v[1].x+bb[1], v[2].x+bb[2], v[3].x+bb[3]);
        float4 l1 = make_float4(v[4].x+bb[4], v[5].x+bb[5], v[6].x+bb[6], v[7].x+bb[7]);
        float4 h0 = make_float4(v[0].y+bb[0], v[1].y+bb[1], v[2].y+bb[2], v[3].y+bb[3]);
        float4 h1 = make_float4(v[4].y+bb[4], v[5].y+bb[5], v[6].y+bb[6], v[7].y+bb[7]);
        *(float4*)p0 = l0; *(float4*)(p0 + 4) = l1;
        *(float4*)p1 = h0; *(float4*)(p1 + 4) = h1;
    }
}

// ---------------- persistent bi-LSTM layer (f32x2 k-pair packed) ------------
static constexpr int GPD  = 74;
static constexpr int KP   = 806;   // padded Whh row stride (floats) — conflict-free
static constexpr int RMAX = 48;
static constexpr int KC   = 80;    // k chunk (10 chunks)
static constexpr int HA_S = 41;    // hA2 u64 stride per batch row
static constexpr int LSTM_SMEM = RMAX*KP*4 + NB*HA_S*8 + RMAX*33*4 + 12*32*4;

__global__ __launch_bounds__(128) void lstm_kernel(
    const float* __restrict__ xs_f, const float* __restrict__ xs_b,
    const float* __restrict__ Whh_f, const float* __restrict__ Whh_b,
    float* __restrict__ hout, unsigned* __restrict__ ctr)
{
    extern __shared__ __align__(16) float smem_[];
    float* Wsm = smem_;
    u64*  hA2  = (u64*)(smem_ + RMAX * KP);
    float* gsm = (float*)(hA2 + NB * HA_S);
    float* csm = gsm + RMAX * 33;

    const int dir = blockIdx.x / GPD;
    const int g   = blockIdx.x - dir * GPD;
    const float* xs  = dir ? xs_b : xs_f;
    const float* Whh = dir ? Whh_b : Whh_f;
    const int dirOff = dir ? HH : 0;
    unsigned* myc = ctr + dir;

    const int S  = (g < 60) ? 11 : 10;
    const int j0 = (g < 60) ? g * 11 : 660 + (g - 60) * 10;
    const int R  = 4 * S;
    const int tid = threadIdx.x;

    // stage Whh slice rows into smem (pad rows zeroed)
    for (int r = 0; r < RMAX; r++) {
        if (r < R) {
            int gi = r / S, jl = r - gi * S;
            const float* src = Whh + (size_t)(gi * HH + j0 + jl) * HH;
            for (int k = tid; k < HH; k += 128) Wsm[r * KP + k] = src[k];
        } else {
            for (int k = tid; k < HH; k += 128) Wsm[r * KP + k] = 0.0f;
        }
    }
    __syncthreads();

    const int rg = tid >> 3;   // 0..15: rows rg*3..rg*3+2
    const int bg = tid & 7;    // 0..7 : batches bg, bg+8, bg+16, bg+24

    const u32 Wa = (u32)__cvta_generic_to_shared(Wsm);
    const u32 Ha = (u32)__cvta_generic_to_shared(hA2);

    // per-thread h-chunk fill offsets (10 u64 per chunk)
    int goff[10], soff[10];
#pragma unroll
    for (int i = 0; i < 10; i++) {
        int e = i * 128 + tid;
        int b = e / 40, kp = e - b * 40;
        goff[i] = b * HC + 2 * kp;
        soff[i] = b * HA_S + kp;
    }

    // per-thread gate-row metadata + x prefetch setup
    int growv[3]; bool rok[3];
#pragma unroll
    for (int q = 0; q < 3; q++) {
        int r = rg * 3 + q;
        rok[q] = (r < R);
        int gi = r / S;
        growv[q] = rok[q] ? (gi * HH + j0 + (r - gi * S)) : 0;
    }
    const int t0 = dir ? (TT - 1) : 0;
    float xv[12], xn[12];
    {
        const float* xr = xs + (size_t)t0 * NB * HG;
#pragma unroll
        for (int q = 0; q < 3; q++)
#pragma unroll
            for (int j = 0; j < 4; j++)
                xv[q*4+j] = rok[q] ? xr[(size_t)(bg + 8*j) * HG + growv[q]] : 0.0f;
    }

    for (int s = 0; s < TT; s++) {
        const int t = dir ? (TT - 1 - s) : s;
        if (s + 1 < TT) {
            const int tn = dir ? (t - 1) : (t + 1);
            const float* xr = xs + (size_t)tn * NB * HG;
#pragma unroll
            for (int q = 0; q < 3; q++)
#pragma unroll
                for (int j = 0; j < 4; j++)
                    xn[q*4+j] = rok[q] ? xr[(size_t)(bg + 8*j) * HG + growv[q]] : 0.0f;
        }

        u64 acc[3][4];
#pragma unroll
        for (int q = 0; q < 3; q++)
#pragma unroll
            for (int j = 0; j < 4; j++) acc[q][j] = 0ull;

        if (s > 0) {
            const int tp = dir ? (t + 1) : (t - 1);
            const float* hsrc = hout + (size_t)tp * NB * HC + dirOff;
            u64 pre[10];
#pragma unroll
            for (int i = 0; i < 10; i++) pre[i] = *(const u64*)(hsrc + goff[i]);
            for (int ck = 0; ck < 10; ck++) {
#pragma unroll
                for (int i = 0; i < 10; i++) hA2[soff[i]] = pre[i];
                __syncthreads();
                if (ck < 9) {
                    const float* p = hsrc + (ck + 1) * KC;
#pragma unroll
                    for (int i = 0; i < 10; i++) pre[i] = *(const u64*)(p + goff[i]);
                }
                u32 w0a = Wa + (u32)(((rg*3 + 0) * KP + ck * KC) * 4);
                u32 w1a = w0a + KP * 4;
                u32 w2a = w1a + KP * 4;
                u32 ha  = Ha + (u32)(bg * (HA_S * 8));
#pragma unroll 10
                for (int kp = 0; kp < 40; kp++) {
                    u64 w0 = lds64(w0a), w1 = lds64(w1a), w2 = lds64(w2a);
                    u64 h0 = lds64(ha);
                    u64 h1 = lds64(ha + 8 * HA_S * 8);
                    u64 h2 = lds64(ha + 16 * HA_S * 8);
                    u64 h3 = lds64(ha + 24 * HA_S * 8);
                    w0a += 8; w1a += 8; w2a += 8; ha += 8;
                    fma2(acc[0][0], w0, h0); fma2(acc[0][1], w0, h1);
                    fma2(acc[0][2], w0, h2); fma2(acc[0][3], w0, h3);
                    fma2(acc[1][0], w1, h0); fma2(acc[1][1], w1, h1);
                    fma2(acc[1][2], w1, h2); fma2(acc[1][3], w1, h3);
                    fma2(acc[2][0], w2, h0); fma2(acc[2][1], w2, h1);
                    fma2(acc[2][2], w2, h2); fma2(acc[2][3], w2, h3);
                }
                __syncthreads();
            }
        }

        // gate pre-activations = recurrent + precomputed input gates
#pragma unroll
        for (int q = 0; q < 3; q++) {
            int r = rg * 3 + q;
            if (rok[q]) {
#pragma unroll
                for (int j = 0; j < 4; j++) {
                    float2 v = unpack2(acc[q][j]);
                    int b = bg + 8 * j;
                    gsm[r * 33 + b] = v.x + v.y + xv[q*4+j];
                }
            }
        }
        __syncthreads();

        for (int it = tid; it < S * 32; it += 128) {
            int jl = it >> 5, b = it & 31;
            float gi = gsm[(0 * S + jl) * 33 + b];
            float gf = gsm[(1 * S + jl) * 33 + b];
            float gg = gsm[(2 * S + jl) * 33 + b];
            float go = gsm[(3 * S + jl) * 33 + b];
            float c  = (s == 0) ? 0.0f : csm[it];
            float cn = sigm(gf) * c + sigm(gi) * tanh_acc(gg);
            float hn = sigm(go) * tanh_acc(cn);
            csm[it] = cn;
            hout[(size_t)t * NB * HC + (size_t)b * HC + dirOff + j0 + jl] = hn;
        }
        __threadfence();
        __syncthreads();
        if (tid == 0) {
            atomicAdd(myc, 1u);
            unsigned tgt = (unsigned)(s + 1) * (unsigned)GPD;
            while (*((volatile unsigned*)myc) < tgt) { }
            __threadfence();
        }
        __syncthreads();
#pragma unroll
        for (int i = 0; i < 12; i++) xv[i] = xn[i];
    }
}

// ---------------- logits -> softmax -> (sin, cos) numerators ----------------
__global__ __launch_bounds__(128) void head_kernel(
    const float* __restrict__ h2, const float* __restrict__ Wl,
    const float* __restrict__ bl, const float* __restrict__ alph,
    float* __restrict__ sc)
{
    __shared__ float row[HC];
    __shared__ float lg[24];
    const int m = blockIdx.x;
    const float* src = h2 + (size_t)m * HC;
    for (int k = threadIdx.x; k < HC; k += 128) row[k] = src[k];
    __syncthreads();

    const int w = threadIdx.x >> 5, lane = threadIdx.x & 31;
    for (int a = w; a < NA; a += 4) {
        const float* wr = Wl + (size_t)a * HC;
        float sum = 0.0f;
        for (int k = lane; k < HC; k += 32) sum += row[k] * wr[k];
#pragma unroll
        for (int o = 16; o; o >>= 1) sum += __shfl_xor_sync(0xffffffffu, sum, o);
        if (lane == 0) lg[a] = sum + bl[a];
    }
    __syncthreads();

    if (threadIdx.x < 32) {
        int a = threadIdx.x;
        float l = (a < NA) ? lg[a] : -1e30f;
        float mx = l;
#pragma unroll
        for (int o = 16; o; o >>= 1) mx = fmaxf(mx, __shfl_xor_sync(0xffffffffu, mx, o));
        float e = (a < NA) ? expf(l - mx) : 0.0f;
        float ss = e;
#pragma unroll
        for (int o = 16; o; o >>= 1) ss += __shfl_xor_sync(0xffffffffu, ss, o);
        float p = e / ss;
#pragma unroll
        for (int k = 0; k < 3; k++) {
            float sy = 0.0f, sx = 0.0f;
            if (a < NA) {
                float al = alph[a * 3 + k];
                sy = p * sinf(al);
                sx = p * cosf(al);
            }
#pragma unroll
            for (int o = 16; o; o >>= 1) {
                sy += __shfl_xor_sync(0xffffffffu, sy, o);
                sx += __shfl_xor_sync(0xffffffffu, sx, o);
            }
            if (a == 0) {
                sc[(size_t)(m * 3 + k) * 2 + 0] = sy;
                sc[(size_t)(m * 3 + k) * 2 + 1] = sx;
            }
        }
    }
}

// ---------------- NeRF coordinate chain (fp64, trig-free) -------------------
__global__ __launch_bounds__(32) void coords_kernel(
    const float* __restrict__ sc, float* __restrict__ out)
{
    const int b = threadIdx.x;
    if (b >= NB) return;
    const double blen[3] = {1.458, 1.525, 1.33};
    const double bangv[3] = {2.124, 1.941, 2.028};
    double rct[3], rst[3];
#pragma unroll
    for (int k = 0; k < 3; k++) {
        rct[k] = blen[k] * cos(bangv[k]);
        rst[k] = blen[k] * sin(bangv[k]);
    }
    double ax=0, ay=0, az=0, bx=1.458, by=0, bz=0, cx=2.0, cy=1.0, cz=0;

    for (int t = 0; t < TT; t++) {
#pragma unroll
        for (int k = 0; k < 3; k++) {
            size_t mi = ((size_t)t * NB + b) * 0 + (size_t)(t * 3 + k); // angle idx t,k
            // sc layout: [(t*NB + bb)*3 + k] per-batch — recompute properly:
            size_t base = (((size_t)t * NB + b) * 3 + k) * 2;
            double sy = (double)sc[base + 0];
            double sx = (double)sc[base + 1];
            double ir = 1.0 / sqrt(sx * sx + sy * sy);
            double cp = sx * ir, sp = sy * ir;

            double ux = cx - bx, uy = cy - by, uz = cz - bz;
            double inv = 1.0 / sqrt(ux*ux + uy*uy + uz*uz);
            ux *= inv; uy *= inv; uz *= inv;
            double vx = bx - ax, vy = by - ay, vz = bz - az;
            double nx = vy*uz - vz*uy, ny = vz*ux - vx*uz, nz = vx*uy - vy*ux;
            inv = 1.0 / sqrt(nx*nx + ny*ny + nz*nz);
            nx *= inv; ny *= inv; nz *= inv;
            double mx = ny*uz - nz*uy, my = nz*ux - nx*uz, mz = nx*uy - ny*ux;
            double dx = cx - rct[k]*ux + rst[k]*(cp*mx + sp*nx);
            double dy = cy - rct[k]*uy + rst[k]*(cp*my + sp*ny);
            double dz = cz - rct[k]*uz + rst[k]*(cp*mz + sp*nz);
            size_t i = (size_t)(t * 3 + k);
            out[(i * NB + b) * 3 + 0] = (float)dx;
            out[(i * NB + b) * 3 + 1] = (float)dy;
            out[(i * NB + b) * 3 + 2] = (float)dz;
            (void)mi;
            ax = bx; ay = by; az = bz;
            bx = cx; by = cy; bz = cz;
            cx = dx; cy = dy; cz = dz;
        }
    }
}

extern "C" void kernel_launch(void* const* d_in, const int* in_sizes, int n_in,
                              void* d_out, int out_size) {
    const float* x       = (const float*)d_in[0];
    const float* Wih_f0  = (const float*)d_in[1];
    const float* Whh_f0  = (const float*)d_in[2];
    const float* b_f0    = (const float*)d_in[3];
    const float* Wih_b0  = (const float*)d_in[4];
    const float* Whh_b0  = (const float*)d_in[5];
    const float* b_b0    = (const float*)d_in[6];
    const float* Wih_f1  = (const float*)d_in[7];
    const float* Whh_f1  = (const float*)d_in[8];
    const float* b_f1    = (const float*)d_in[9];
    const float* Wih_b1  = (const float*)d_in[10];
    const float* Whh_b1  = (const float*)d_in[11];
    const float* b_b1    = (const float*)d_in[12];
    const float* Wl      = (const float*)d_in[13];
    const float* bl      = (const float*)d_in[14];
    const float* alph    = (const float*)d_in[15];
    float* out = (float*)d_out;

    float *bufA, *bufB, *h1, *h2, *sc;
    unsigned* ctr;
    cudaGetSymbolAddress((void**)&bufA, g_bufA);
    cudaGetSymbolAddress((void**)&bufB, g_bufB);
    cudaGetSymbolAddress((void**)&h1,   g_h1);
    cudaGetSymbolAddress((void**)&h2,   g_h2);
    cudaGetSymbolAddress((void**)&sc,   g_sc);
    cudaGetSymbolAddress((void**)&ctr,  g_ctr);

    cudaFuncSetAttribute(lstm_kernel,
                         cudaFuncAttributeMaxDynamicSharedMemorySize, LSTM_SMEM);

    const int M = TT * NB;
    dim3 gdim(HG / 128, M / 256);

    init_kernel<<<1, 32>>>();
    gemm_bias<<<gdim, 256>>>(x, Wih_f0, b_f0, bufA, M, HG, DIN);
    gemm_bias<<<gdim, 256>>>(x, Wih_b0, b_b0, bufB, M, HG, DIN);
    lstm_kernel<<<2 * GPD, 128, LSTM_SMEM>>>(bufA, bufB, Whh_f0, Whh_b0, h1, ctr);
    gemm_bias<<<gdim, 256>>>(h1, Wih_f1, b_f1, bufA, M, HG, HC);
    gemm_bias<<<gdim, 256>>>(h1, Wih_b1, b_b1, bufB, M, HG, HC);
    lstm_kernel<<<2 * GPD, 128, LSTM_SMEM>>>(bufA, bufB, Whh_f1, Whh_b1, h2, ctr + 2);
    head_kernel<<<M, 128>>>(h2, Wl, bl, alph, sc);
    coords_kernel<<<1, 32>>>(sc, out);
}

// round 11
// speedup vs baseline: 1.5146x; 1.1497x over previous
#include <cuda_runtime.h>
#include <math.h>
#include <stdint.h>

typedef unsigned long long u64;
typedef unsigned int u32;

static constexpr int TT  = 512;
static constexpr int NB  = 32;
static constexpr int DIN = 41;
static constexpr int HH  = 800;
static constexpr int HG  = 3200;   // 4H
static constexpr int HC  = 1600;   // 2H
static constexpr int NA  = 20;

// scratch (device globals; allocation is forbidden)
__device__ __align__(16) float g_bufA[(size_t)TT * NB * HG];
__device__ __align__(16) float g_bufB[(size_t)TT * NB * HG];
__device__ __align__(16) float g_h1[(size_t)TT * NB * HC];
__device__ __align__(16) float g_h2[(size_t)TT * NB * HC];
__device__ __align__(16) float g_sc[(size_t)TT * NB * 6];   // (sy,sx) per angle
__device__ unsigned g_ctr[4];

__global__ void init_kernel() {
    if (threadIdx.x < 4) g_ctr[threadIdx.x] = 0u;
}

__device__ __forceinline__ float sigm(float x) { return 1.0f / (1.0f + expf(-x)); }
__device__ __forceinline__ float tanh_acc(float x) {
    float e = expf(-2.0f * fabsf(x));
    return copysignf((1.0f - e) / (1.0f + e), x);
}

// ---- packed f32x2 helpers (Blackwell FFMA2 path) ---------------------------
__device__ __forceinline__ void fma2(u64& acc, u64 a, u64 b) {
    asm("fma.rn.f32x2 %0, %1, %2, %0;" : "+l"(acc) : "l"(a), "l"(b));
}
__device__ __forceinline__ u64 pack2(float x, float y) {
    u64 r; asm("mov.b64 %0, {%1, %2};" : "=l"(r) : "f"(x), "f"(y)); return r;
}
__device__ __forceinline__ float2 unpack2(u64 v) {
    float2 f; asm("mov.b64 {%0, %1}, %2;" : "=f"(f.x), "=f"(f.y) : "l"(v)); return f;
}
__device__ __forceinline__ u64 lds64(u32 a) {
    u64 r; asm volatile("ld.shared.b64 %0, [%1];" : "=l"(r) : "r"(a)); return r;
}
__device__ __forceinline__ void lds128_2(u64& x, u64& y, u32 a) {
    asm volatile("ld.shared.v2.b64 {%0, %1}, [%2];" : "=l"(x), "=l"(y) : "r"(a));
}

// ---------------- SGEMM (f32x2): C[M,N] = A[M,K] @ W[N,K]^T + bias[N] -------
__device__ __forceinline__ void fetch_tileA(
    const float* __restrict__ A, int M, int K, int bm, int k0, int tid,
    bool vec, float4 av[4])
{
#pragma unroll
    for (int i = 0; i < 4; i++) {
        int e = i * 256 + tid, m = e >> 2, c4 = e & 3;
        int gm = bm + m, gk = k0 + c4 * 4;
        const float* p = A + (size_t)gm * K + gk;
        if (vec && gk + 4 <= K) av[i] = *(const float4*)p;
        else {
            float r[4];
#pragma unroll
            for (int u = 0; u < 4; u++) r[u] = (gk + u < K) ? p[u] : 0.0f;
            av[i] = make_float4(r[0], r[1], r[2], r[3]);
        }
    }
}
__device__ __forceinline__ void fetch_tileW(
    const float* __restrict__ W, int N, int K, int bn, int k0, int tid,
    bool vec, float4 wv[2])
{
#pragma unroll
    for (int i = 0; i < 2; i++) {
        int e = i * 256 + tid, n = e >> 2, c4 = e & 3;
        int gn = bn + n, gk = k0 + c4 * 4;
        const float* p = W + (size_t)gn * K + gk;
        if (vec && gk + 4 <= K) wv[i] = *(const float4*)p;
        else {
            float r[4];
#pragma unroll
            for (int u = 0; u < 4; u++) r[u] = (gk + u < K) ? p[u] : 0.0f;
            wv[i] = make_float4(r[0], r[1], r[2], r[3]);
        }
    }
}

__global__ __launch_bounds__(256) void gemm_bias(
    const float* __restrict__ A, const float* __restrict__ W,
    const float* __restrict__ bias, float* __restrict__ C,
    int M, int N, int K)
{
    __shared__ __align__(16) float As[16][260];
    __shared__ __align__(16) float Ws[16][132];
    const int bm = blockIdx.y * 256, bn = blockIdx.x * 128;
    const int tid = threadIdx.x, tx = tid & 15, ty = tid >> 4;
    const bool vec = ((K & 3) == 0);

    u64 acc[8][8];
#pragma unroll
    for (int i = 0; i < 8; i++)
#pragma unroll
        for (int j = 0; j < 8; j++) acc[i][j] = 0ull;

    const int nch = (K + 15) / 16;
    float4 av[4], wv[2];
    fetch_tileA(A, M, K, bm, 0, tid, vec, av);
    fetch_tileW(W, N, K, bn, 0, tid, vec, wv);
#pragma unroll
    for (int i = 0; i < 4; i++) {
        int e = i * 256 + tid, m = e >> 2, c4 = e & 3;
        As[c4*4+0][m] = av[i].x; As[c4*4+1][m] = av[i].y;
        As[c4*4+2][m] = av[i].z; As[c4*4+3][m] = av[i].w;
    }
#pragma unroll
    for (int i = 0; i < 2; i++) {
        int e = i * 256 + tid, n = e >> 2, c4 = e & 3;
        Ws[c4*4+0][n] = wv[i].x; Ws[c4*4+1][n] = wv[i].y;
        Ws[c4*4+2][n] = wv[i].z; Ws[c4*4+3][n] = wv[i].w;
    }
    __syncthreads();

    const u32 asA = (u32)__cvta_generic_to_shared(&As[0][0]) + (u32)(ty * 64);

    for (int c = 0; c < nch; c++) {
        float4 av2[4], wv2[2];
        if (c + 1 < nch) {
            fetch_tileA(A, M, K, bm, (c + 1) * 16, tid, vec, av2);
            fetch_tileW(W, N, K, bn, (c + 1) * 16, tid, vec, wv2);
        }
#pragma unroll
        for (int kk = 0; kk < 16; kk++) {
            u64 a[8];
            u32 aa = asA + (u32)(kk * 1040);
            lds128_2(a[0], a[1], aa);
            lds128_2(a[2], a[3], aa + 16);
            lds128_2(a[4], a[5], aa + 32);
            lds128_2(a[6], a[7], aa + 48);
            float4 w0 = *(const float4*)&Ws[kk][tx * 8];
            float4 w1 = *(const float4*)&Ws[kk][tx * 8 + 4];
            u64 wd[8];
            wd[0] = pack2(w0.x, w0.x); wd[1] = pack2(w0.y, w0.y);
            wd[2] = pack2(w0.z, w0.z); wd[3] = pack2(w0.w, w0.w);
            wd[4] = pack2(w1.x, w1.x); wd[5] = pack2(w1.y, w1.y);
            wd[6] = pack2(w1.z, w1.z); wd[7] = pack2(w1.w, w1.w);
#pragma unroll
            for (int mp = 0; mp < 8; mp++)
#pragma unroll
                for (int j = 0; j < 8; j++) fma2(acc[mp][j], a[mp], wd[j]);
        }
        __syncthreads();
        if (c + 1 < nch) {
#pragma unroll
            for (int i = 0; i < 4; i++) {
                int e = i * 256 + tid, m = e >> 2, c4 = e & 3;
                As[c4*4+0][m] = av2[i].x; As[c4*4+1][m] = av2[i].y;
                As[c4*4+2][m] = av2[i].z; As[c4*4+3][m] = av2[i].w;
            }
#pragma unroll
            for (int i = 0; i < 2; i++) {
                int e = i * 256 + tid, n = e >> 2, c4 = e & 3;
                Ws[c4*4+0][n] = wv2[i].x; Ws[c4*4+1][n] = wv2[i].y;
                Ws[c4*4+2][n] = wv2[i].z; Ws[c4*4+3][n] = wv2[i].w;
            }
            __syncthreads();
        }
    }

    const int gn = bn + tx * 8;
    float bb[8];
#pragma unroll
    for (int j = 0; j < 8; j++) bb[j] = bias[gn + j];
#pragma unroll
    for (int mp = 0; mp < 8; mp++) {
        float2 v[8];
#pragma unroll
        for (int j = 0; j < 8; j++) v[j] = unpack2(acc[mp][j]);
        int gm = bm + ty * 16 + mp * 2;
        float* p0 = C + (size_t)gm * N + gn;
        float* p1 = p0 + N;
        float4 l0 = make_float4(v[0].x+bb[0], v[1].x+bb[1], v[2].x+bb[2], v[3].x+bb[3]);
        float4 l1 = make_float4(v[4].x+bb[4], v[5].x+bb[5], v[6].x+bb[6], v[7].x+bb[7]);
        float4 h0 = make_float4(v[0].y+bb[0], v[1].y+bb[1], v[2].y+bb[2], v[3].y+bb[3]);
        float4 h1 = make_float4(v[4].y+bb[4], v[5].y+bb[5], v[6].y+bb[6], v[7].y+bb[7]);
        *(float4*)p0 = l0; *(float4*)(p0 + 4) = l1;
        *(float4*)p1 = h0; *(float4*)(p1 + 4) = h1;
    }
}

// ---------------- persistent bi-LSTM layer (f32x2, 256 thr, k-split) --------
// 256 threads = 8 warps = 2/SMSP. Threads 0-127 reduce k in [0,400) floats,
// threads 128-255 reduce k in [400,800). Each half keeps the 3-row x 4-batch
// microtile (7 LDS / 12 FFMA2). Partial sums land in gsm0/gsm1, summed in the
// activation phase.
static constexpr int GPD  = 74;
static constexpr int KP   = 806;   // padded Whh row stride (floats)
static constexpr int RMAX = 48;
static constexpr int KC   = 80;    // k chunk in floats (40 k-pairs); 5 chunks/half
static constexpr int HA_S = 41;    // u64 stride per batch row in h staging
static constexpr int LSTM_SMEM = RMAX*KP*4 + 2*NB*HA_S*8 + 2*RMAX*33*4 + 12*32*4;

__global__ __launch_bounds__(256) void lstm_kernel(
    const float* __restrict__ xs_f, const float* __restrict__ xs_b,
    const float* __restrict__ Whh_f, const float* __restrict__ Whh_b,
    float* __restrict__ hout, unsigned* __restrict__ ctr)
{
    extern __shared__ __align__(16) float smem_[];
    float* Wsm = smem_;                                   // RMAX*KP
    u64*  hA2  = (u64*)(smem_ + RMAX * KP);               // 2 * NB * HA_S
    float* gsm0 = (float*)(hA2 + 2 * NB * HA_S);          // RMAX*33
    float* gsm1 = gsm0 + RMAX * 33;                       // RMAX*33
    float* csm  = gsm1 + RMAX * 33;                       // 12*32

    const int dir = blockIdx.x / GPD;
    const int g   = blockIdx.x - dir * GPD;
    const float* xs  = dir ? xs_b : xs_f;
    const float* Whh = dir ? Whh_b : Whh_f;
    const int dirOff = dir ? HH : 0;
    unsigned* myc = ctr + dir;

    const int S  = (g < 60) ? 11 : 10;
    const int j0 = (g < 60) ? g * 11 : 660 + (g - 60) * 10;
    const int R  = 4 * S;
    const int tid = threadIdx.x;
    const int kh  = tid >> 7;       // k-half: 0 or 1
    const int t7  = tid & 127;
    const int rg  = t7 >> 3;        // 0..15 -> rows rg*3..rg*3+2
    const int bg  = t7 & 7;         // batches bg, bg+8, bg+16, bg+24

    // stage Whh slice rows into smem (pad rows zeroed)
    for (int r = 0; r < RMAX; r++) {
        if (r < R) {
            int gi = r / S, jl = r - gi * S;
            const float* src = Whh + (size_t)(gi * HH + j0 + jl) * HH;
            for (int k = tid; k < HH; k += 256) Wsm[r * KP + k] = src[k];
        } else {
            for (int k = tid; k < HH; k += 256) Wsm[r * KP + k] = 0.0f;
        }
    }
    __syncthreads();

    const u32 Wa  = (u32)__cvta_generic_to_shared(Wsm);
    const u32 Hah = (u32)__cvta_generic_to_shared(hA2) + (u32)(kh * NB * HA_S * 8);
    u64* myhA = hA2 + kh * NB * HA_S;
    float* mygsm = kh ? gsm1 : gsm0;

    // per-thread h-staging offsets (10 u64 per chunk, over 128 threads of half)
    int goff[10], soff[10];
#pragma unroll
    for (int i = 0; i < 10; i++) {
        int e = i * 128 + t7;
        int b = e / 40, kp = e - b * 40;
        goff[i] = b * HC + 2 * kp;
        soff[i] = b * HA_S + kp;
    }

    // per-thread gate-row metadata + x prefetch (half 0 only)
    int growv[3]; bool rok[3];
#pragma unroll
    for (int q = 0; q < 3; q++) {
        int r = rg * 3 + q;
        rok[q] = (r < R);
        int gi = r / S;
        growv[q] = rok[q] ? (gi * HH + j0 + (r - gi * S)) : 0;
    }
    const int t0 = dir ? (TT - 1) : 0;
    float xv[12], xn[12];
    if (kh == 0) {
        const float* xr = xs + (size_t)t0 * NB * HG;
#pragma unroll
        for (int q = 0; q < 3; q++)
#pragma unroll
            for (int j = 0; j < 4; j++)
                xv[q*4+j] = rok[q] ? xr[(size_t)(bg + 8*j) * HG + growv[q]] : 0.0f;
    }

    const int ck0 = kh * 5;   // this half's first chunk

    for (int s = 0; s < TT; s++) {
        const int t = dir ? (TT - 1 - s) : s;
        if (kh == 0 && s + 1 < TT) {
            const int tn = dir ? (t - 1) : (t + 1);
            const float* xr = xs + (size_t)tn * NB * HG;
#pragma unroll
            for (int q = 0; q < 3; q++)
#pragma unroll
                for (int j = 0; j < 4; j++)
                    xn[q*4+j] = rok[q] ? xr[(size_t)(bg + 8*j) * HG + growv[q]] : 0.0f;
        }

        u64 acc[3][4];
#pragma unroll
        for (int q = 0; q < 3; q++)
#pragma unroll
            for (int j = 0; j < 4; j++) acc[q][j] = 0ull;

        if (s > 0) {
            const int tp = dir ? (t + 1) : (t - 1);
            const float* base0 = hout + (size_t)tp * NB * HC + dirOff + ck0 * KC;
            u64 pre[10];
#pragma unroll
            for (int i = 0; i < 10; i++) pre[i] = *(const u64*)(base0 + goff[i]);
            for (int c = 0; c < 5; c++) {
#pragma unroll
                for (int i = 0; i < 10; i++) myhA[soff[i]] = pre[i];
                __syncthreads();
                if (c < 4) {
                    const float* p = base0 + (c + 1) * KC;
#pragma unroll
                    for (int i = 0; i < 10; i++) pre[i] = *(const u64*)(p + goff[i]);
                }
                u32 w0a = Wa + (u32)(((rg*3 + 0) * KP + (ck0 + c) * KC) * 4);
                u32 w1a = w0a + KP * 4;
                u32 w2a = w1a + KP * 4;
                u32 ha  = Hah + (u32)(bg * (HA_S * 8));
#pragma unroll 10
                for (int kp = 0; kp < 40; kp++) {
                    u64 w0 = lds64(w0a), w1 = lds64(w1a), w2 = lds64(w2a);
                    u64 h0 = lds64(ha);
                    u64 h1 = lds64(ha + 8 * HA_S * 8);
                    u64 h2 = lds64(ha + 16 * HA_S * 8);
                    u64 h3 = lds64(ha + 24 * HA_S * 8);
                    w0a += 8; w1a += 8; w2a += 8; ha += 8;
                    fma2(acc[0][0], w0, h0); fma2(acc[0][1], w0, h1);
                    fma2(acc[0][2], w0, h2); fma2(acc[0][3], w0, h3);
                    fma2(acc[1][0], w1, h0); fma2(acc[1][1], w1, h1);
                    fma2(acc[1][2], w1, h2); fma2(acc[1][3], w1, h3);
                    fma2(acc[2][0], w2, h0); fma2(acc[2][1], w2, h1);
                    fma2(acc[2][2], w2, h2); fma2(acc[2][3], w2, h3);
                }
                __syncthreads();
            }
        }

        // partial gate pre-activations (half 0 folds in the input gates)
#pragma unroll
        for (int q = 0; q < 3; q++) {
            int r = rg * 3 + q;
            if (rok[q]) {
#pragma unroll
                for (int j = 0; j < 4; j++) {
                    float2 v = unpack2(acc[q][j]);
                    int b = bg + 8 * j;
                    float val = v.x + v.y;
                    if (kh == 0) val += xv[q*4+j];
                    mygsm[r * 33 + b] = val;
                }
            }
        }
        __syncthreads();

        for (int it = tid; it < S * 32; it += 256) {
            int jl = it >> 5, b = it & 31;
            float gi = gsm0[(0 * S + jl) * 33 + b] + gsm1[(0 * S + jl) * 33 + b];
            float gf = gsm0[(1 * S + jl) * 33 + b] + gsm1[(1 * S + jl) * 33 + b];
            float gg = gsm0[(2 * S + jl) * 33 + b] + gsm1[(2 * S + jl) * 33 + b];
            float go = gsm0[(3 * S + jl) * 33 + b] + gsm1[(3 * S + jl) * 33 + b];
            float c  = (s == 0) ? 0.0f : csm[it];
            float cn = sigm(gf) * c + sigm(gi) * tanh_acc(gg);
            float hn = sigm(go) * tanh_acc(cn);
            csm[it] = cn;
            hout[(size_t)t * NB * HC + (size_t)b * HC + dirOff + j0 + jl] = hn;
        }
        __threadfence();
        __syncthreads();
        if (tid == 0) {
            atomicAdd(myc, 1u);
            unsigned tgt = (unsigned)(s + 1) * (unsigned)GPD;
            while (*((volatile unsigned*)myc) < tgt) { }
            __threadfence();
        }
        __syncthreads();
        if (kh == 0) {
#pragma unroll
            for (int i = 0; i < 12; i++) xv[i] = xn[i];
        }
    }
}

// ---------------- logits -> softmax -> (sin, cos) numerators ----------------
__global__ __launch_bounds__(128) void head_kernel(
    const float* __restrict__ h2, const float* __restrict__ Wl,
    const float* __restrict__ bl, const float* __restrict__ alph,
    float* __restrict__ sc)
{
    __shared__ float row[HC];
    __shared__ float lg[24];
    const int m = blockIdx.x;
    const float* src = h2 + (size_t)m * HC;
    for (int k = threadIdx.x; k < HC; k += 128) row[k] = src[k];
    __syncthreads();

    const int w = threadIdx.x >> 5, lane = threadIdx.x & 31;
    for (int a = w; a < NA; a += 4) {
        const float* wr = Wl + (size_t)a * HC;
        float sum = 0.0f;
        for (int k = lane; k < HC; k += 32) sum += row[k] * wr[k];
#pragma unroll
        for (int o = 16; o; o >>= 1) sum += __shfl_xor_sync(0xffffffffu, sum, o);
        if (lane == 0) lg[a] = sum + bl[a];
    }
    __syncthreads();

    if (threadIdx.x < 32) {
        int a = threadIdx.x;
        float l = (a < NA) ? lg[a] : -1e30f;
        float mx = l;
#pragma unroll
        for (int o = 16; o; o >>= 1) mx = fmaxf(mx, __shfl_xor_sync(0xffffffffu, mx, o));
        float e = (a < NA) ? expf(l - mx) : 0.0f;
        float ss = e;
#pragma unroll
        for (int o = 16; o; o >>= 1) ss += __shfl_xor_sync(0xffffffffu, ss, o);
        float p = e / ss;
#pragma unroll
        for (int k = 0; k < 3; k++) {
            float sy = 0.0f, sx = 0.0f;
            if (a < NA) {
                float al = alph[a * 3 + k];
                sy = p * sinf(al);
                sx = p * cosf(al);
            }
#pragma unroll
            for (int o = 16; o; o >>= 1) {
                sy += __shfl_xor_sync(0xffffffffu, sy, o);
                sx += __shfl_xor_sync(0xffffffffu, sx, o);
            }
            if (a == 0) {
                sc[(size_t)(m * 3 + k) * 2 + 0] = sy;
                sc[(size_t)(m * 3 + k) * 2 + 1] = sx;
            }
        }
    }
}

// ---------------- NeRF coordinate chain (fp64, trig-free) -------------------
__global__ __launch_bounds__(32) void coords_kernel(
    const float* __restrict__ sc, float* __restrict__ out)
{
    const int b = threadIdx.x;
    if (b >= NB) return;
    const double blen[3] = {1.458, 1.525, 1.33};
    const double bangv[3] = {2.124, 1.941, 2.028};
    double rct[3], rst[3];
#pragma unroll
    for (int k = 0; k < 3; k++) {
        rct[k] = blen[k] * cos(bangv[k]);
        rst[k] = blen[k] * sin(bangv[k]);
    }
    double ax=0, ay=0, az=0, bx=1.458, by=0, bz=0, cx=2.0, cy=1.0, cz=0;

    for (int t = 0; t < TT; t++) {
#pragma unroll
        for (int k = 0; k < 3; k++) {
            size_t base = (((size_t)t * NB + b) * 3 + k) * 2;
            double sy = (double)sc[base + 0];
            double sx = (double)sc[base + 1];
            double ir = 1.0 / sqrt(sx * sx + sy * sy);
            double cp = sx * ir, sp = sy * ir;

            double ux = cx - bx, uy = cy - by, uz = cz - bz;
            double inv = 1.0 / sqrt(ux*ux + uy*uy + uz*uz);
            ux *= inv; uy *= inv; uz *= inv;
            double vx = bx - ax, vy = by - ay, vz = bz - az;
            double nx = vy*uz - vz*uy, ny = vz*ux - vx*uz, nz = vx*uy - vy*ux;
            inv = 1.0 / sqrt(nx*nx + ny*ny + nz*nz);
            nx *= inv; ny *= inv; nz *= inv;
            double mx = ny*uz - nz*uy, my = nz*ux - nx*uz, mz = nx*uy - ny*ux;
            double dx = cx - rct[k]*ux + rst[k]*(cp*mx + sp*nx);
            double dy = cy - rct[k]*uy + rst[k]*(cp*my + sp*ny);
            double dz = cz - rct[k]*uz + rst[k]*(cp*mz + sp*nz);
            size_t i = (size_t)(t * 3 + k);
            out[(i * NB + b) * 3 + 0] = (float)dx;
            out[(i * NB + b) * 3 + 1] = (float)dy;
            out[(i * NB + b) * 3 + 2] = (float)dz;
            ax = bx; ay = by; az = bz;
            bx = cx; by = cy; bz = cz;
            cx = dx; cy = dy; cz = dz;
        }
    }
}

extern "C" void kernel_launch(void* const* d_in, const int* in_sizes, int n_in,
                              void* d_out, int out_size) {
    const float* x       = (const float*)d_in[0];
    const float* Wih_f0  = (const float*)d_in[1];
    const float* Whh_f0  = (const float*)d_in[2];
    const float* b_f0    = (const float*)d_in[3];
    const float* Wih_b0  = (const float*)d_in[4];
    const float* Whh_b0  = (const float*)d_in[5];
    const float* b_b0    = (const float*)d_in[6];
    const float* Wih_f1  = (const float*)d_in[7];
    const float* Whh_f1  = (const float*)d_in[8];
    const float* b_f1    = (const float*)d_in[9];
    const float* Wih_b1  = (const float*)d_in[10];
    const float* Whh_b1  = (const float*)d_in[11];
    const float* b_b1    = (const float*)d_in[12];
    const float* Wl      = (const float*)d_in[13];
    const float* bl      = (const float*)d_in[14];
    const float* alph    = (const float*)d_in[15];
    float* out = (float*)d_out;

    float *bufA, *bufB, *h1, *h2, *sc;
    unsigned* ctr;
    cudaGetSymbolAddress((void**)&bufA, g_bufA);
    cudaGetSymbolAddress((void**)&bufB, g_bufB);
    cudaGetSymbolAddress((void**)&h1,   g_h1);
    cudaGetSymbolAddress((void**)&h2,   g_h2);
    cudaGetSymbolAddress((void**)&sc,   g_sc);
    cudaGetSymbolAddress((void**)&ctr,  g_ctr);

    cudaFuncSetAttribute(lstm_kernel,
                         cudaFuncAttributeMaxDynamicSharedMemorySize, LSTM_SMEM);

    const int M = TT * NB;
    dim3 gdim(HG / 128, M / 256);

    init_kernel<<<1, 32>>>();
    gemm_bias<<<gdim, 256>>>(x, Wih_f0, b_f0, bufA, M, HG, DIN);
    gemm_bias<<<gdim, 256>>>(x, Wih_b0, b_b0, bufB, M, HG, DIN);
    lstm_kernel<<<2 * GPD, 256, LSTM_SMEM>>>(bufA, bufB, Whh_f0, Whh_b0, h1, ctr);
    gemm_bias<<<gdim, 256>>>(h1, Wih_f1, b_f1, bufA, M, HG, HC);
    gemm_bias<<<gdim, 256>>>(h1, Wih_b1, b_b1, bufB, M, HG, HC);
    lstm_kernel<<<2 * GPD, 256, LSTM_SMEM>>>(bufA, bufB, Whh_f1, Whh_b1, h2, ctr + 2);
    head_kernel<<<M, 128>>>(h2, Wl, bl, alph, sc);
    coords_kernel<<<1, 32>>>(sc, out);
}